// round 4
// baseline (speedup 1.0000x reference)
#include <cuda_runtime.h>
#include <cuda_fp16.h>

#define Bq 8
#define Sq 1024
#define Dm 1024
#define NH 16
#define DH 64
#define NEGV (-1e9f)

#define PSH 1032   // half score/P row stride
#define TS  72     // half tile row stride (144B -> +4 banks/row, LDSM conflict-free)

// ---- scratch (device globals: allocation-free rule) ----
__device__ __half g_Hh[(size_t)Bq*Sq*Dm];
__device__ __half g_Q[(size_t)Bq*NH*Sq*DH];
__device__ __half g_K[(size_t)Bq*NH*Sq*DH];
__device__ __half g_V[(size_t)Bq*NH*Sq*DH];
__device__ __half g_heads[(size_t)Bq*Sq*Dm];
__device__ __half g_Woh[(size_t)Dm*Dm];

// ---- helpers ----
__device__ __forceinline__ void mma_f16(float c[4], const unsigned a[4],
                                        unsigned b0, unsigned b1) {
    asm volatile(
        "mma.sync.aligned.m16n8k16.row.col.f32.f16.f16.f32 "
        "{%0,%1,%2,%3}, {%4,%5,%6,%7}, {%8,%9}, {%0,%1,%2,%3};"
        : "+f"(c[0]), "+f"(c[1]), "+f"(c[2]), "+f"(c[3])
        : "r"(a[0]), "r"(a[1]), "r"(a[2]), "r"(a[3]), "r"(b0), "r"(b1));
}
__device__ __forceinline__ unsigned sptr(const void* p) {
    return (unsigned)__cvta_generic_to_shared(p);
}
__device__ __forceinline__ void ldm_x4(unsigned r[4], unsigned addr) {
    asm volatile("ldmatrix.sync.aligned.m8n8.x4.shared.b16 {%0,%1,%2,%3}, [%4];"
                 : "=r"(r[0]), "=r"(r[1]), "=r"(r[2]), "=r"(r[3]) : "r"(addr));
}
__device__ __forceinline__ void ldm_x4_t(unsigned r[4], unsigned addr) {
    asm volatile("ldmatrix.sync.aligned.m8n8.x4.trans.shared.b16 {%0,%1,%2,%3}, [%4];"
                 : "=r"(r[0]), "=r"(r[1]), "=r"(r[2]), "=r"(r[3]) : "r"(addr));
}
__device__ __forceinline__ void cpa16(unsigned dst, const void* src) {
    asm volatile("cp.async.cg.shared.global [%0], [%1], 16;" :: "r"(dst), "l"(src));
}
#define CPA_COMMIT() asm volatile("cp.async.commit_group;")
#define CPA_WAIT(n)  asm volatile("cp.async.wait_group %0;" :: "n"(n))

// ============================================================================
// K0a: Wo f32 -> half.  K0b: H f32 -> half.
// ============================================================================
__global__ void wconv_kernel(const float* __restrict__ Wo) {
    int i = (blockIdx.x * 256 + threadIdx.x) * 4;
    float4 v = *(const float4*)&Wo[i];
    __half2* dst = (__half2*)&g_Woh[i];
    dst[0] = __floats2half2_rn(v.x, v.y);
    dst[1] = __floats2half2_rn(v.z, v.w);
}
__global__ void hconv_kernel(const float* __restrict__ H) {
    int i = (blockIdx.x * 256 + threadIdx.x) * 4;
    float4 v = *(const float4*)&H[i];
    __half2* dst = (__half2*)&g_Hh[i];
    dst[0] = __floats2half2_rn(v.x, v.y);
    dst[1] = __floats2half2_rn(v.z, v.w);
}

// ============================================================================
// K1: fused QKV projection, fp16 mma + ldmatrix. grid (64, NH), 256 thr.
// ============================================================================
__global__ void __launch_bounds__(256) qkv_kernel(
    const float* __restrict__ Wq, const float* __restrict__ bq,
    const float* __restrict__ Wk, const float* __restrict__ bk,
    const float* __restrict__ Wv, const float* __restrict__ bv)
{
    extern __shared__ __half hsm[];
    __half* Hs = hsm;               // 128 x 72
    __half* Ws = hsm + 128 * TS;    // 3 x 64 x 72

    const int tid  = threadIdx.x;
    const int lane = tid & 31;
    const int warp = tid >> 5;
    const int g = lane >> 3, rr = lane & 7;
    const int warpM = warp >> 1;   // 0..3: 32 rows
    const int warpN = warp & 1;    // 0..1: 32 cols
    const int h    = blockIdx.y;
    const int row0 = blockIdx.x * 128;
    const int b    = row0 >> 10;
    const int s    = row0 & 1023;

    // H tile via cp.async
    for (int i = tid; i < 128 * 8; i += 256) {
        int r = i >> 3, q = i & 7;
        cpa16(sptr(&Hs[r * TS + q * 8]),
              g_Hh + (size_t)(row0 + r) * Dm + h * DH + q * 8);
    }
    CPA_COMMIT();

    // weights f32 -> half smem (3 x 64x64)
    const float* Wt[3] = {Wq, Wk, Wv};
    for (int wsel = 0; wsel < 3; wsel++) {
        const float* W = Wt[wsel] + h * DH * DH;
        __half* Wd = Ws + wsel * 64 * TS;
        for (int i = tid; i < 64 * 16; i += 256) {
            int r = i >> 4, q = i & 15;
            float4 v = *(const float4*)&W[r * DH + q * 4];
            __half2* dst = (__half2*)&Wd[r * TS + q * 4];
            dst[0] = __floats2half2_rn(v.x, v.y);
            dst[1] = __floats2half2_rn(v.z, v.w);
        }
    }
    CPA_WAIT(0);
    __syncthreads();

    // A fragments (loop-invariant across wsel)
    unsigned a[4][2][4];
    #pragma unroll
    for (int ks = 0; ks < 4; ks++)
        #pragma unroll
        for (int mi = 0; mi < 2; mi++) {
            int row = warpM * 32 + mi * 16 + rr + (g & 1) * 8;
            int col = ks * 16 + (g >> 1) * 8;
            ldm_x4(a[ks][mi], sptr(&Hs[row * TS + col]));
        }

    const float* bt[3] = {bq, bk, bv};
    __half*      Ot[3] = {g_Q, g_K, g_V};

    #pragma unroll
    for (int wsel = 0; wsel < 3; wsel++) {
        const __half* Wd = Ws + wsel * 64 * TS;
        float c[2][4][4];
        #pragma unroll
        for (int mi = 0; mi < 2; mi++)
            #pragma unroll
            for (int t = 0; t < 4; t++)
                #pragma unroll
                for (int q = 0; q < 4; q++) c[mi][t][q] = 0.f;

        #pragma unroll
        for (int ks = 0; ks < 4; ks++) {
            #pragma unroll
            for (int hn = 0; hn < 2; hn++) {
                int row = warpN * 32 + hn * 16 + rr + (g >> 1) * 8;
                int col = ks * 16 + (g & 1) * 8;
                unsigned bb[4];
                ldm_x4(bb, sptr(&Wd[row * TS + col]));
                #pragma unroll
                for (int mi = 0; mi < 2; mi++) {
                    mma_f16(c[mi][hn * 2 + 0], a[ks][mi], bb[0], bb[1]);
                    mma_f16(c[mi][hn * 2 + 1], a[ks][mi], bb[2], bb[3]);
                }
            }
        }

        const float* bias = bt[wsel] + h * DH;
        __half* O = Ot[wsel] + ((size_t)(b * NH + h) * Sq + s) * DH;
        #pragma unroll
        for (int mi = 0; mi < 2; mi++)
            #pragma unroll
            for (int t = 0; t < 4; t++) {
                int r  = warpM * 32 + mi * 16 + (lane >> 2);
                int cN = warpN * 32 + t * 8 + (lane & 3) * 2;
                float b0v = bias[cN], b1v = bias[cN + 1];
                *(__half2*)&O[(size_t)r * DH + cN] =
                    __floats2half2_rn(c[mi][t][0] + b0v, c[mi][t][1] + b1v);
                *(__half2*)&O[(size_t)(r + 8) * DH + cN] =
                    __floats2half2_rn(c[mi][t][2] + b0v, c[mi][t][3] + b1v);
            }
    }
}

// ============================================================================
// K2: attention. 64-row query tile, 512 thr (16 warps). grid (NH, 16, Bq).
// 3-stage cp.async ring, ONE sync per tile. Vectorized softmax.
// ============================================================================
__global__ void __launch_bounds__(512) attn_kernel(
    const int* __restrict__ mask, float* __restrict__ Aout)
{
    extern __shared__ __half hsm[];
    __half* psh = hsm;                 // 64 x 1032: scores -> P
    __half* Qs  = psh + 64 * PSH;      // 64 x 72
    __half* KVs = Qs + 64 * TS;        // 3 x 128 x 72 ring

    const int tid = threadIdx.x, lane = tid & 31, warp = tid >> 5;
    const int h = blockIdx.x, b = blockIdx.z, s0 = blockIdx.y * 64;
    const int g = lane >> 3, rr = lane & 7;
    const int warpM = warp >> 2;   // 0..3: 16 rows
    const int warpN = warp & 3;    // 0..3: 32 keys / 16 head-cols

    const __half* Qg = g_Q + ((size_t)(b * NH + h) * Sq + s0) * DH;
    const __half* Kg = g_K + (size_t)(b * NH + h) * Sq * DH;
    const __half* Vg = g_V + (size_t)(b * NH + h) * Sq * DH;

    auto issue = [&](const __half* src, int buf) {
        __half* dst = KVs + buf * 128 * TS;
        for (int i = tid; i < 128 * 8; i += 512) {
            int r = i >> 3, q = i & 7;
            cpa16(sptr(&dst[r * TS + q * 8]), src + (size_t)r * DH + q * 8);
        }
        CPA_COMMIT();
    };

    issue(Kg, 0);
    issue(Kg + 128 * DH, 1);

    // Q tile 64x64
    for (int i = tid; i < 64 * 8; i += 512) {
        int r = i >> 3, q = i & 7;
        *(uint4*)&Qs[r * TS + q * 8] = ((const uint4*)Qg)[r * 8 + q];
    }
    __syncthreads();

    // Q fragments (loop-invariant)
    unsigned qa[4][4];
    #pragma unroll
    for (int ks = 0; ks < 4; ks++) {
        int row = warpM * 16 + rr + (g & 1) * 8;
        int col = ks * 16 + (g >> 1) * 8;
        ldm_x4(qa[ks], sptr(&Qs[row * TS + col]));
    }

    // ---- Phase A: scores = Q K^T / 8 -> half smem ----
    for (int kt = 0; kt < 8; kt++) {
        if (kt < 6) { issue(Kg + (size_t)(kt + 2) * 128 * DH, (kt + 2) % 3); CPA_WAIT(2); }
        else if (kt == 6) CPA_WAIT(1);
        else              CPA_WAIT(0);
        __syncthreads();
        const __half* Kt = KVs + (kt % 3) * 128 * TS;

        float c[4][4];
        #pragma unroll
        for (int t = 0; t < 4; t++)
            #pragma unroll
            for (int q = 0; q < 4; q++) c[t][q] = 0.f;

        #pragma unroll
        for (int ks = 0; ks < 4; ks++) {
            #pragma unroll
            for (int hn = 0; hn < 2; hn++) {
                int row = warpN * 32 + hn * 16 + rr + (g >> 1) * 8;
                int col = ks * 16 + (g & 1) * 8;
                unsigned bb[4];
                ldm_x4(bb, sptr(&Kt[row * TS + col]));
                mma_f16(c[hn * 2 + 0], qa[ks], bb[0], bb[1]);
                mma_f16(c[hn * 2 + 1], qa[ks], bb[2], bb[3]);
            }
        }
        int r = warpM * 16 + (lane >> 2);
        #pragma unroll
        for (int t = 0; t < 4; t++) {
            int cN = kt * 128 + warpN * 32 + t * 8 + (lane & 3) * 2;
            *(__half2*)&psh[r * PSH + cN] =
                __floats2half2_rn(c[t][0] * 0.125f, c[t][1] * 0.125f);
            *(__half2*)&psh[(r + 8) * PSH + cN] =
                __floats2half2_rn(c[t][2] * 0.125f, c[t][3] * 0.125f);
        }
    }
    __syncthreads();   // psh complete; K buffers free

    // overlap V tile loads with softmax
    issue(Vg, 0);
    issue(Vg + 128 * DH, 1);

    // ---- softmax: warp w owns rows 4w..4w+3; vectorized x4 ----
    #pragma unroll
    for (int ri = 0; ri < 4; ri++) {
        int r = warp * 4 + ri;
        const int4* mrow4 = (const int4*)(mask + ((size_t)b * Sq + s0 + r) * Sq);
        float sv[32];
        float mx = NEGV;
        #pragma unroll
        for (int t = 0; t < 8; t++) {
            int j = t * 128 + lane * 4;
            int4 m = mrow4[t * 32 + lane];
            __half2 p01 = *(__half2*)&psh[r * PSH + j];
            __half2 p23 = *(__half2*)&psh[r * PSH + j + 2];
            float s0v = m.x ? __low2float(p01)  : NEGV;
            float s1v = m.y ? __high2float(p01) : NEGV;
            float s2v = m.z ? __low2float(p23)  : NEGV;
            float s3v = m.w ? __high2float(p23) : NEGV;
            sv[t * 4 + 0] = s0v; sv[t * 4 + 1] = s1v;
            sv[t * 4 + 2] = s2v; sv[t * 4 + 3] = s3v;
            mx = fmaxf(mx, fmaxf(fmaxf(s0v, s1v), fmaxf(s2v, s3v)));
        }
        #pragma unroll
        for (int o = 16; o; o >>= 1) mx = fmaxf(mx, __shfl_xor_sync(~0u, mx, o));
        float sum = 0.f;
        #pragma unroll
        for (int t = 0; t < 32; t++) {
            float e = __expf(sv[t] - mx);
            sv[t] = e;
            sum += e;
        }
        #pragma unroll
        for (int o = 16; o; o >>= 1) sum += __shfl_xor_sync(~0u, sum, o);
        float inv = 1.0f / sum;
        float4* Ar4 = (float4*)(Aout + (((size_t)h * Bq + b) * Sq + s0 + r) * Sq);
        #pragma unroll
        for (int t = 0; t < 8; t++) {
            int j = t * 128 + lane * 4;
            float a0 = sv[t * 4] * inv, a1 = sv[t * 4 + 1] * inv;
            float a2 = sv[t * 4 + 2] * inv, a3 = sv[t * 4 + 3] * inv;
            __stcs(&Ar4[t * 32 + lane], make_float4(a0, a1, a2, a3));
            *(__half2*)&psh[r * PSH + j]     = __floats2half2_rn(a0, a1);
            *(__half2*)&psh[r * PSH + j + 2] = __floats2half2_rn(a2, a3);
        }
    }
    __syncthreads();   // P complete

    // ---- Phase B: heads(64x64) = P @ V ----
    float c2[2][4];
    #pragma unroll
    for (int t = 0; t < 2; t++)
        #pragma unroll
        for (int q = 0; q < 4; q++) c2[t][q] = 0.f;

    const int n0 = warpN * 16;
    for (int kt = 0; kt < 8; kt++) {
        if (kt < 6) { issue(Vg + (size_t)(kt + 2) * 128 * DH, (kt + 2) % 3); CPA_WAIT(2); }
        else if (kt == 6) CPA_WAIT(1);
        else              CPA_WAIT(0);
        __syncthreads();
        const __half* Vt = KVs + (kt % 3) * 128 * TS;

        #pragma unroll
        for (int k0 = 0; k0 < 128; k0 += 16) {
            unsigned a[4];
            int arow = warpM * 16 + rr + (g & 1) * 8;
            int acol = kt * 128 + k0 + (g >> 1) * 8;
            ldm_x4(a, sptr(&psh[arow * PSH + acol]));
            unsigned bb[4];
            int brow = k0 + rr + (g & 1) * 8;
            int bcol = n0 + (g >> 1) * 8;
            ldm_x4_t(bb, sptr(&Vt[brow * TS + bcol]));
            mma_f16(c2[0], a, bb[0], bb[1]);
            mma_f16(c2[1], a, bb[2], bb[3]);
        }
    }

    {
        int r = warpM * 16 + (lane >> 2);
        size_t base = ((size_t)(b * Sq + s0)) * Dm + h * DH;
        #pragma unroll
        for (int t = 0; t < 2; t++) {
            int cN = n0 + t * 8 + (lane & 3) * 2;
            *(__half2*)&g_heads[base + (size_t)r * Dm + cN] =
                __floats2half2_rn(c2[t][0], c2[t][1]);
            *(__half2*)&g_heads[base + (size_t)(r + 8) * Dm + cN] =
                __floats2half2_rn(c2[t][2], c2[t][3]);
        }
    }
}

// ============================================================================
// K3: out = heads @ Woh^T + bo. fp16 mma, tile 128x128, cp.async 2-stage.
// grid (64, 8), 256 thr.
// ============================================================================
__global__ void __launch_bounds__(256) out_kernel(
    const float* __restrict__ bo, float* __restrict__ out)
{
    extern __shared__ __half hsm[];
    __half* As = hsm;                  // 2 x 128 x 72
    __half* Bs = hsm + 2 * 128 * TS;   // 2 x 128 x 72

    const int tid = threadIdx.x, lane = tid & 31, warp = tid >> 5;
    const int g = lane >> 3, rr = lane & 7;
    const int warpM = warp >> 2;   // 0..1: 64 rows
    const int warpN = warp & 3;    // 0..3: 32 cols
    const int r0 = blockIdx.x * 128, n0 = blockIdx.y * 128;

    auto issue = [&](int kt, int buf) {
        __half* ad = As + buf * 128 * TS;
        __half* bd = Bs + buf * 128 * TS;
        const __half* as = g_heads + (size_t)r0 * Dm + kt * 64;
        const __half* bs = g_Woh   + (size_t)n0 * Dm + kt * 64;
        for (int i = tid; i < 128 * 8; i += 256) {
            int r = i >> 3, q = i & 7;
            cpa16(sptr(&ad[r * TS + q * 8]), as + (size_t)r * Dm + q * 8);
        }
        for (int i = tid; i < 128 * 8; i += 256) {
            int r = i >> 3, q = i & 7;
            cpa16(sptr(&bd[r * TS + q * 8]), bs + (size_t)r * Dm + q * 8);
        }
        CPA_COMMIT();
    };

    float c[4][4][4];
    #pragma unroll
    for (int mi = 0; mi < 4; mi++)
        #pragma unroll
        for (int nt = 0; nt < 4; nt++)
            #pragma unroll
            for (int q = 0; q < 4; q++) c[mi][nt][q] = 0.f;

    issue(0, 0);

    for (int kt = 0; kt < 16; kt++) {
        if (kt < 15) { issue(kt + 1, (kt + 1) & 1); CPA_WAIT(1); }
        else         { CPA_WAIT(0); }
        __syncthreads();
        const __half* At = As + (kt & 1) * 128 * TS;
        const __half* Bt = Bs + (kt & 1) * 128 * TS;

        #pragma unroll
        for (int ks = 0; ks < 4; ks++) {
            int k0 = ks * 16;
            unsigned a[4][4];
            #pragma unroll
            for (int mi = 0; mi < 4; mi++) {
                int row = warpM * 64 + mi * 16 + rr + (g & 1) * 8;
                int col = k0 + (g >> 1) * 8;
                ldm_x4(a[mi], sptr(&At[row * TS + col]));
            }
            unsigned bb[2][4];
            #pragma unroll
            for (int hn = 0; hn < 2; hn++) {
                int row = warpN * 32 + hn * 16 + rr + (g >> 1) * 8;
                int col = k0 + (g & 1) * 8;
                ldm_x4(bb[hn], sptr(&Bt[row * TS + col]));
            }
            #pragma unroll
            for (int mi = 0; mi < 4; mi++) {
                mma_f16(c[mi][0], a[mi], bb[0][0], bb[0][1]);
                mma_f16(c[mi][1], a[mi], bb[0][2], bb[0][3]);
                mma_f16(c[mi][2], a[mi], bb[1][0], bb[1][1]);
                mma_f16(c[mi][3], a[mi], bb[1][2], bb[1][3]);
            }
        }
        __syncthreads();
    }

    #pragma unroll
    for (int mi = 0; mi < 4; mi++) {
        #pragma unroll
        for (int nt = 0; nt < 4; nt++) {
            int r  = r0 + warpM * 64 + mi * 16 + (lane >> 2);
            int cN = n0 + warpN * 32 + nt * 8 + (lane & 3) * 2;
            float b0v = bo[cN], b1v = bo[cN + 1];
            out[(size_t)r * Dm + cN]           = c[mi][nt][0] + b0v;
            out[(size_t)r * Dm + cN + 1]       = c[mi][nt][1] + b1v;
            out[(size_t)(r + 8) * Dm + cN]     = c[mi][nt][2] + b0v;
            out[(size_t)(r + 8) * Dm + cN + 1] = c[mi][nt][3] + b1v;
        }
    }
}

// ============================================================================
extern "C" void kernel_launch(void* const* d_in, const int* in_sizes, int n_in,
                              void* d_out, int out_size)
{
    const float* H    = (const float*)d_in[0];
    const int*   mask = (const int*)  d_in[1];
    const float* Wq   = (const float*)d_in[2];
    const float* bq   = (const float*)d_in[3];
    const float* Wk   = (const float*)d_in[4];
    const float* bk   = (const float*)d_in[5];
    const float* Wv   = (const float*)d_in[6];
    const float* bv   = (const float*)d_in[7];
    const float* Wo   = (const float*)d_in[8];
    const float* bo   = (const float*)d_in[9];

    float* out  = (float*)d_out;
    float* Aout = out + (size_t)Bq * Sq * Dm;

    const int smem1 = (128 * TS + 3 * 64 * TS) * sizeof(__half);            // 46080
    const int smem2 = (64 * PSH + 64 * TS + 3 * 128 * TS) * sizeof(__half); // 196608
    const int smem3 = 4 * 128 * TS * sizeof(__half);                        // 73728

    cudaFuncSetAttribute(qkv_kernel,  cudaFuncAttributeMaxDynamicSharedMemorySize, smem1);
    cudaFuncSetAttribute(attn_kernel, cudaFuncAttributeMaxDynamicSharedMemorySize, smem2);
    cudaFuncSetAttribute(out_kernel,  cudaFuncAttributeMaxDynamicSharedMemorySize, smem3);

    wconv_kernel<<<1024, 256>>>(Wo);
    hconv_kernel<<<8192, 256>>>(H);
    qkv_kernel<<<dim3(64, NH), 256, smem1>>>(Wq, bq, Wk, bk, Wv, bv);
    attn_kernel<<<dim3(NH, 16, Bq), 512, smem2>>>(mask, Aout);
    out_kernel<<<dim3(64, 8), 256, smem3>>>(bo, out);
}